// round 10
// baseline (speedup 1.0000x reference)
#include <cuda_runtime.h>
#include <cstdint>

#define NN 2048
#define IN_DIM 1024
#define MLPW 16
#define HIDD 256
#define L2DIM 64
#define NCLS 4

// ---------------- scratch (device globals; no allocation) ----------------
__device__ float g_A[(size_t)NN * NN];        // A = adj*mask + I (tf32-rounded)
__device__ float g_Xt[(size_t)NN * IN_DIM];   // tf32-rounded x [2048][1024]
__device__ float g_Bt1[(size_t)HIDD * IN_DIM];// tf32-rounded Wg1 TRANSPOSED [256][1024]
__device__ float g_XWt[(size_t)HIDD * NN];    // dc-scaled x@Wg1 TRANSPOSED [256][2048], tf32
__device__ float g_AXW[4][(size_t)NN * HIDD]; // dr-scaled A@XW split-K partials (fp32)
__device__ float g_HW[(size_t)NN * NCLS];     // dc-scaled hid@Wg2
__device__ float g_rowsum[NN];
__device__ float g_colsum[NN];

__device__ __forceinline__ float rsqrt_pos(float v) {
    return v > 0.f ? rsqrtf(v) : 0.f;
}
__device__ __forceinline__ uint32_t f2tf32(float f) {
    uint32_t u;
    asm("cvt.rna.tf32.f32 %0, %1;" : "=r"(u) : "f"(f));
    return u;
}

// ---------------- async copy / ldmatrix helpers ----------------------------
__device__ __forceinline__ void cp_async16(uint32_t smem, const void* gptr) {
    asm volatile("cp.async.cg.shared.global [%0], [%1], 16;\n" ::"r"(smem), "l"(gptr));
}
__device__ __forceinline__ void cp_commit() {
    asm volatile("cp.async.commit_group;\n");
}
template <int N>
__device__ __forceinline__ void cp_wait() {
    asm volatile("cp.async.wait_group %0;\n" ::"n"(N));
}
__device__ __forceinline__ void ldsm4(uint32_t* r, uint32_t addr) {
    asm volatile("ldmatrix.sync.aligned.m8n8.x4.shared.b16 {%0,%1,%2,%3}, [%4];"
                 : "=r"(r[0]), "=r"(r[1]), "=r"(r[2]), "=r"(r[3]) : "r"(addr));
}
__device__ __forceinline__ void mma_tf32(float* c,
                                         const uint32_t* a,
                                         uint32_t b0, uint32_t b1) {
    asm volatile(
        "mma.sync.aligned.m16n8k8.row.col.f32.tf32.tf32.f32 "
        "{%0,%1,%2,%3}, {%4,%5,%6,%7}, {%8,%9}, {%0,%1,%2,%3};"
        : "+f"(c[0]), "+f"(c[1]), "+f"(c[2]), "+f"(c[3])
        : "r"(a[0]), "r"(a[1]), "r"(a[2]), "r"(a[3]), "r"(b0), "r"(b1));
}

// ---------------- kernel 1: round x + transpose-round Wg1 + zero colsum ----
__global__ __launch_bounds__(256) void round_xw_kernel(const float* __restrict__ x,
                                                       const float* __restrict__ Wg1) {
    int b = blockIdx.x, tid = threadIdx.x;
    if (b < 512) {
        size_t idx4 = (size_t)b * 1024 + tid;
        const float4* src = reinterpret_cast<const float4*>(x);
        float4* dst = reinterpret_cast<float4*>(g_Xt);
#pragma unroll
        for (int t = 0; t < 4; t++) {
            float4 v = src[idx4 + t * 256];
            uint4 u;
            u.x = f2tf32(v.x); u.y = f2tf32(v.y); u.z = f2tf32(v.z); u.w = f2tf32(v.w);
            dst[idx4 + t * 256] = *reinterpret_cast<float4*>(&u);
        }
    } else if (b < 768) {
        // transpose + round Wg1 [1024][256] -> g_Bt1 [256][1024], 32x32 tiles
        __shared__ float s[32][33];
        int t = b - 512;             // 0..255
        int kt = t >> 3;             // 0..31  k-tile
        int nt = t & 7;              // 0..7   n-tile
        int tr = tid >> 3, tc = tid & 7;
        float4 v = *reinterpret_cast<const float4*>(
            &Wg1[(size_t)(kt * 32 + tr) * HIDD + nt * 32 + tc * 4]);
        s[tr][tc * 4 + 0] = __uint_as_float(f2tf32(v.x));
        s[tr][tc * 4 + 1] = __uint_as_float(f2tf32(v.y));
        s[tr][tc * 4 + 2] = __uint_as_float(f2tf32(v.z));
        s[tr][tc * 4 + 3] = __uint_as_float(f2tf32(v.w));
        __syncthreads();
        float4 w;
        w.x = s[tc * 4 + 0][tr];
        w.y = s[tc * 4 + 1][tr];
        w.z = s[tc * 4 + 2][tr];
        w.w = s[tc * 4 + 3][tr];
        *reinterpret_cast<float4*>(
            &g_Bt1[(size_t)(nt * 32 + tr) * IN_DIM + kt * 32 + tc * 4]) = w;
    } else {
        // zero colsum (edge_kernel accumulates into it atomically)
#pragma unroll
        for (int t = 0; t < 8; t++) g_colsum[tid + t * 256] = 0.f;
    }
}

// ---------------- kernel 2: edge MLP -> A, rowsum, fused colsum ------------
// 256 blocks x 8 rows; colsum partials kept in registers, one atomicAdd
// per (thread, column-slot) at the end.
__global__ __launch_bounds__(256) void edge_kernel(
    const float* __restrict__ adj, const float* __restrict__ xdeg,
    const float* __restrict__ ydeg, const float* __restrict__ Wm1,
    const float* __restrict__ bm1, const float* __restrict__ Wm2,
    const float* __restrict__ bm2) {
    __shared__ float sW1[48], sb1[16], sdw[16], sb2[2];
    int tid = threadIdx.x;
    if (tid < 48) sW1[tid] = Wm1[tid];
    if (tid < 16) sb1[tid] = bm1[tid];
    if (tid < 16) sdw[tid] = Wm2[2 * tid + 1] - Wm2[2 * tid];
    if (tid < 2)  sb2[tid] = bm2[tid];
    __syncthreads();

    const float db = sb2[1] - sb2[0];
    const int r0 = blockIdx.x * 8;

    float csum[8] = {};
    float rsum[8];

#pragma unroll
    for (int r = 0; r < 8; r++) {
        const int i = r0 + r;
        const float* arow = adj  + (size_t)i * NN;
        const float* xrow = xdeg + (size_t)i * NN;
        const float* yrow = ydeg + (size_t)i * NN;
        float* Arow = g_A + (size_t)i * NN;
        float rs = 0.f;
#pragma unroll
        for (int t = 0; t < 8; t++) {
            int j = tid + t * 256;
            float a = arow[j], xd = xrow[j], yd = yrow[j];
            float dl = db;
#pragma unroll
            for (int k = 0; k < MLPW; k++) {
                float h = fmaf(a, sW1[k], fmaf(xd, sW1[16 + k], fmaf(yd, sW1[32 + k], sb1[k])));
                h = fmaxf(h, 0.f);
                dl = fmaf(h, sdw[k], dl);
            }
            float d = 0.5f * dl;
            float th;
            asm("tanh.approx.f32 %0, %1;" : "=f"(th) : "f"(d));
            float mask = fmaf(0.5f, th, 0.5f);
            float Av = a * mask + (j == i ? 1.f : 0.f);
            Av = __uint_as_float(f2tf32(Av));
            Arow[j] = Av;
            rs += Av;
            csum[t] += Av;
        }
        rsum[r] = rs;
    }

    // per-row reductions (8 rows)
#pragma unroll
    for (int r = 0; r < 8; r++)
        for (int off = 16; off; off >>= 1)
            rsum[r] += __shfl_down_sync(0xffffffffu, rsum[r], off);
    __shared__ float red[8][8];   // [warp][row]
    if ((tid & 31) == 0) {
        int w = tid >> 5;
#pragma unroll
        for (int r = 0; r < 8; r++) red[w][r] = rsum[r];
    }
    __syncthreads();
    if (tid < 8) {
        float s = 0.f;
#pragma unroll
        for (int w = 0; w < 8; w++) s += red[w][tid];
        g_rowsum[r0 + tid] = s;
    }

    // fused colsum: spread-address atomics (524K total across grid)
#pragma unroll
    for (int t = 0; t < 8; t++)
        atomicAdd(&g_colsum[tid + t * 256], csum[t]);
}

// ---------------- tf32 tensor-core GEMM, BK=64, 2-stage, split-K CTAs -----
#define BKK 64
#define HSB 8192      // half-stage bytes per operand (64 rows * 128B)
#define OPB 16384     // per-stage per-operand bytes
#define GEMM_SMEM 65536

template <bool TRANSOUT, int NSPLIT, bool SCALE>
__device__ __forceinline__ void gemm_body(const float* __restrict__ A,
                                          const float* __restrict__ Bt,
                                          float* __restrict__ C, int Kd,
                                          const float* __restrict__ sumvec) {
    extern __shared__ __align__(16) uint8_t smem_dyn[];
    const uint32_t sAu = (uint32_t)__cvta_generic_to_shared(smem_dyn);
    const uint32_t sBu = sAu + 2 * OPB;

    const int tid = threadIdx.x;
    const int lane = tid & 31, warp = tid >> 5;
    const int wm = warp & 1, wn = (warp >> 1) & 1, kg = warp >> 2;  // kg 0..1
    const int gid = lane >> 2, tig = lane & 3;
    const int mi = lane >> 3, lr = lane & 7;
    const int bm0 = blockIdx.y * 64, bn0 = blockIdx.x * 64;
    const int kbase = (NSPLIT > 1) ? blockIdx.z * (Kd / NSPLIT) : 0;

    const int ld_row = tid >> 2;           // 0..63
    const int qb = (tid & 3) << 1;         // 0,2,4,6
    const uint32_t off0 = ld_row * 128 + (((qb + 0) ^ (ld_row & 7)) << 4);
    const uint32_t off1 = ld_row * 128 + (((qb + 1) ^ (ld_row & 7)) << 4);
    const float* Ag = A + (size_t)(bm0 + ld_row) * Kd + kbase;
    const float* Bg = Bt + (size_t)(bn0 + ld_row) * Kd + kbase;

    const int arow = wm * 32 + ((mi & 1) << 3) + lr;
    const int brow = wn * 32 + ((mi >> 1) << 3) + lr;
    const uint32_t axr = arow & 7, bxr = brow & 7;
    const uint32_t qselA = mi >> 1, qselB = mi & 1;
    const uint32_t aOff0 = arow * 128, aOff1 = aOff0 + 16 * 128;
    const uint32_t bOff0 = brow * 128, bOff1 = bOff0 + 16 * 128;
    const uint32_t aqj[2] = {(((uint32_t)(kg * 2 + 0) * 2 + qselA) ^ axr) << 4,
                             (((uint32_t)(kg * 2 + 1) * 2 + qselA) ^ axr) << 4};
    const uint32_t bqj[2] = {(((uint32_t)(kg * 2 + 0) * 2 + qselB) ^ bxr) << 4,
                             (((uint32_t)(kg * 2 + 1) * 2 + qselB) ^ bxr) << 4};

    auto issue = [&](int kt, int s) {
#pragma unroll
        for (int h = 0; h < 2; h++) {
            const float* ag = Ag + (size_t)kt * BKK + h * 32;
            const float* bg = Bg + (size_t)kt * BKK + h * 32;
            uint32_t da = sAu + s * OPB + h * HSB;
            uint32_t db = sBu + s * OPB + h * HSB;
            cp_async16(da + off0, ag + qb * 4);
            cp_async16(da + off1, ag + qb * 4 + 4);
            cp_async16(db + off0, bg + qb * 4);
            cp_async16(db + off1, bg + qb * 4 + 4);
        }
    };

    const int niter = (Kd / NSPLIT) / BKK;
    issue(0, 0);
    cp_commit();

    float acc[2][4][4] = {};

    for (int i = 0; i < niter; i++) {
        cp_wait<0>();
        __syncthreads();
        if (i + 1 < niter) { issue(i + 1, (i + 1) & 1); cp_commit(); }
        const int s = i & 1;
#pragma unroll
        for (int h = 0; h < 2; h++) {
            const uint32_t sAs = sAu + s * OPB + h * HSB;
            const uint32_t sBs = sBu + s * OPB + h * HSB;
#pragma unroll
            for (int jj = 0; jj < 2; jj++) {
                uint32_t af0[4], af1[4], bf0[4], bf1[4];
                ldsm4(af0, sAs + aOff0 + aqj[jj]);
                ldsm4(af1, sAs + aOff1 + aqj[jj]);
                ldsm4(bf0, sBs + bOff0 + bqj[jj]);
                ldsm4(bf1, sBs + bOff1 + bqj[jj]);
                mma_tf32(acc[0][0], af0, bf0[0], bf0[1]);
                mma_tf32(acc[0][1], af0, bf0[2], bf0[3]);
                mma_tf32(acc[0][2], af0, bf1[0], bf1[1]);
                mma_tf32(acc[0][3], af0, bf1[2], bf1[3]);
                mma_tf32(acc[1][0], af1, bf0[0], bf0[1]);
                mma_tf32(acc[1][1], af1, bf0[2], bf0[3]);
                mma_tf32(acc[1][2], af1, bf1[0], bf1[1]);
                mma_tf32(acc[1][3], af1, bf1[2], bf1[3]);
            }
        }
    }

    // ---- 2-way K-split reduction through smem -----------------------------
    __syncthreads();
    float* sred = reinterpret_cast<float*>(smem_dyn);
    const int pi = wm * 2 + wn;
    if (kg == 1) {
#pragma unroll
        for (int mt = 0; mt < 2; mt++)
#pragma unroll
            for (int nt = 0; nt < 4; nt++) {
                int r = mt * 16 + gid, c = nt * 8 + 2 * tig;
                float* base = sred + pi * 1056;
                base[r * 33 + c] = acc[mt][nt][0];
                base[r * 33 + c + 1] = acc[mt][nt][1];
                base[(r + 8) * 33 + c] = acc[mt][nt][2];
                base[(r + 8) * 33 + c + 1] = acc[mt][nt][3];
            }
    }
    __syncthreads();
    if (kg == 0) {
#pragma unroll
        for (int mt = 0; mt < 2; mt++) {
            int r = mt * 16 + gid;
            const float* base = sred + pi * 1056;
            int gr0 = bm0 + wm * 32 + r;
            int gr1 = gr0 + 8;
            float s0 = SCALE ? rsqrt_pos(sumvec[gr0]) : 1.f;
            float s1 = SCALE ? rsqrt_pos(sumvec[gr1]) : 1.f;
#pragma unroll
            for (int nt = 0; nt < 4; nt++) {
                int c = nt * 8 + 2 * tig;
                float v00 = (acc[mt][nt][0] + base[r * 33 + c]) * s0;
                float v01 = (acc[mt][nt][1] + base[r * 33 + c + 1]) * s0;
                float v10 = (acc[mt][nt][2] + base[(r + 8) * 33 + c]) * s1;
                float v11 = (acc[mt][nt][3] + base[(r + 8) * 33 + c + 1]) * s1;
                if (TRANSOUT) {
                    int n0 = bn0 + wn * 32 + c;
                    C[(size_t)n0 * NN + gr0] = __uint_as_float(f2tf32(v00));
                    C[(size_t)(n0 + 1) * NN + gr0] = __uint_as_float(f2tf32(v01));
                    C[(size_t)n0 * NN + gr1] = __uint_as_float(f2tf32(v10));
                    C[(size_t)(n0 + 1) * NN + gr1] = __uint_as_float(f2tf32(v11));
                } else {
                    int col = bn0 + wn * 32 + c;
                    *reinterpret_cast<float2*>(&C[(size_t)gr0 * HIDD + col]) =
                        make_float2(v00, v01);
                    *reinterpret_cast<float2*>(&C[(size_t)gr1 * HIDD + col]) =
                        make_float2(v10, v11);
                }
            }
        }
    }
}

// GEMM1: g_XWt = (dc * (x @ Wg1))^T, tf32-rounded (dc = rsqrt(colsum[m]))
__global__ __launch_bounds__(256) void gemm1_kernel() {
    gemm_body<true, 1, true>(g_Xt, g_Bt1, g_XWt, IN_DIM, g_colsum);
}
// GEMM2: g_AXW[z] = dr * (g_A @ XW) partial over K-quarter z
__global__ __launch_bounds__(256) void gemm2_kernel() {
    gemm_body<false, 4, true>(g_A, g_XWt, g_AXW[blockIdx.z], NN, g_rowsum);
}

// ---------------- hid = (sum_z AXW_z) @ Wl2 + bl2;  HW = dc * (hid @ Wg2) --
__global__ __launch_bounds__(256) void hid_kernel(const float* __restrict__ Wl2,
                                                  const float* __restrict__ bl2,
                                                  const float* __restrict__ Wg2,
                                                  float* __restrict__ hid_out) {
    __shared__ float sAXW[16][HIDD];
    __shared__ float sHid[16][L2DIM + 1];
    int tid = threadIdx.x;
    int rowbase = blockIdx.x * 16;

#pragma unroll
    for (int t = 0; t < 16; t++) {
        size_t idx = (size_t)rowbase * HIDD + tid + t * 256;
        float v = g_AXW[0][idx] + g_AXW[1][idx] + g_AXW[2][idx] + g_AXW[3][idx];
        int li = tid + t * 256;
        sAXW[li >> 8][li & 255] = v;
    }
    __syncthreads();

    int c = tid & 63;
    int rq = tid >> 6;
    float acc[4];
    float b = bl2[c];
#pragma unroll
    for (int it = 0; it < 4; it++) acc[it] = b;
#pragma unroll 4
    for (int k = 0; k < HIDD; k++) {
        float w = __ldg(&Wl2[k * L2DIM + c]);
#pragma unroll
        for (int it = 0; it < 4; it++)
            acc[it] = fmaf(sAXW[it * 4 + rq][k], w, acc[it]);
    }
#pragma unroll
    for (int it = 0; it < 4; it++) {
        int row = it * 4 + rq;
        hid_out[(size_t)(rowbase + row) * L2DIM + c] = acc[it];
        sHid[row][c] = acc[it];
    }
    __syncthreads();
    if (tid < 64) {
        int r = tid >> 2, cls = tid & 3;
        float s = 0.f;
#pragma unroll
        for (int k = 0; k < L2DIM; k++) s = fmaf(sHid[r][k], Wg2[k * NCLS + cls], s);
        g_HW[(size_t)(rowbase + r) * NCLS + cls] = s * rsqrt_pos(g_colsum[rowbase + r]);
    }
}

// ---------------- out[i] = dr[i] * sum_j A[i,j] * HW[j] --------------------
// 256 blocks x 8 rows; HW staged TRANSPOSED (conflict-free float4 reads);
// A rows read as float4.
__global__ __launch_bounds__(256) void out_kernel(float* __restrict__ out) {
    int tid = threadIdx.x;
    __shared__ float sHWt[NCLS][NN];
    const float4* hw4 = reinterpret_cast<const float4*>(g_HW);
#pragma unroll
    for (int t = 0; t < NN / 256; t++) {
        int j = tid + t * 256;
        float4 h = hw4[j];            // HW row j: 4 classes
        sHWt[0][j] = h.x; sHWt[1][j] = h.y; sHWt[2][j] = h.z; sHWt[3][j] = h.w;
    }
    __syncthreads();

    const float4* A4 = reinterpret_cast<const float4*>(g_A);
    __shared__ float red[8][4];
    for (int r = 0; r < 8; r++) {
        int i = blockIdx.x * 8 + r;
        float ax = 0.f, ay = 0.f, az = 0.f, aw = 0.f;
#pragma unroll
        for (int t = 0; t < NN / 1024; t++) {
            int j4 = tid + t * 256;
            float4 a = A4[(size_t)i * (NN / 4) + j4];
            const float4 h0 = *reinterpret_cast<const float4*>(&sHWt[0][j4 * 4]);
            const float4 h1 = *reinterpret_cast<const float4*>(&sHWt[1][j4 * 4]);
            const float4 h2 = *reinterpret_cast<const float4*>(&sHWt[2][j4 * 4]);
            const float4 h3 = *reinterpret_cast<const float4*>(&sHWt[3][j4 * 4]);
            ax += a.x * h0.x + a.y * h0.y + a.z * h0.z + a.w * h0.w;
            ay += a.x * h1.x + a.y * h1.y + a.z * h1.z + a.w * h1.w;
            az += a.x * h2.x + a.y * h2.y + a.z * h2.z + a.w * h2.w;
            aw += a.x * h3.x + a.y * h3.y + a.z * h3.z + a.w * h3.w;
        }
        for (int off = 16; off; off >>= 1) {
            ax += __shfl_down_sync(0xffffffffu, ax, off);
            ay += __shfl_down_sync(0xffffffffu, ay, off);
            az += __shfl_down_sync(0xffffffffu, az, off);
            aw += __shfl_down_sync(0xffffffffu, aw, off);
        }
        if ((tid & 31) == 0) {
            int w = tid >> 5;
            red[w][0] = ax; red[w][1] = ay; red[w][2] = az; red[w][3] = aw;
        }
        __syncthreads();
        if (tid < 4) {
            float s = 0.f;
#pragma unroll
            for (int w = 0; w < 8; w++) s += red[w][tid];
            out[i * NCLS + tid] = rsqrt_pos(g_rowsum[i]) * s;
        }
        __syncthreads();
    }
}

// ---------------- launch (single stream, 6 kernels) ------------------------
extern "C" void kernel_launch(void* const* d_in, const int* in_sizes, int n_in,
                              void* d_out, int out_size) {
    const float* x    = (const float*)d_in[0];
    const float* adj  = (const float*)d_in[1];
    const float* xdeg = (const float*)d_in[2];
    const float* ydeg = (const float*)d_in[3];
    const float* Wm1  = (const float*)d_in[4];
    const float* bm1  = (const float*)d_in[5];
    const float* Wm2  = (const float*)d_in[6];
    const float* bm2  = (const float*)d_in[7];
    const float* Wg1  = (const float*)d_in[8];
    const float* Wl2  = (const float*)d_in[9];
    const float* bl2  = (const float*)d_in[10];
    const float* Wg2  = (const float*)d_in[11];

    float* out = (float*)d_out;               // [2048, 4]
    float* hid = out + (size_t)NN * NCLS;     // [2048, 64]

    static bool attr_done = false;
    if (!attr_done) {   // first call is the (uncaptured) correctness run
        cudaFuncSetAttribute(gemm1_kernel,
                             cudaFuncAttributeMaxDynamicSharedMemorySize, GEMM_SMEM);
        cudaFuncSetAttribute(gemm2_kernel,
                             cudaFuncAttributeMaxDynamicSharedMemorySize, GEMM_SMEM);
        attr_done = true;
    }

    round_xw_kernel<<<769, 256>>>(x, Wg1);
    edge_kernel<<<NN / 8, 256>>>(adj, xdeg, ydeg, Wm1, bm1, Wm2, bm2);
    gemm1_kernel<<<dim3(HIDD / 64, NN / 64, 1), 256, GEMM_SMEM>>>();
    gemm2_kernel<<<dim3(HIDD / 64, NN / 64, 4), 256, GEMM_SMEM>>>();
    hid_kernel<<<NN / 16, 256>>>(Wl2, bl2, Wg2, hid);
    out_kernel<<<NN / 8, 256>>>(out);
}

// round 11
// speedup vs baseline: 1.1655x; 1.1655x over previous
#include <cuda_runtime.h>
#include <cstdint>

#define NN 2048
#define IN_DIM 1024
#define MLPW 16
#define HIDD 256
#define L2DIM 64
#define NCLS 4
#define NSPL 8

// ---------------- scratch (device globals; no allocation) ----------------
__device__ float g_A[(size_t)NN * NN];          // A = adj*mask + I (tf32-rounded)
__device__ float g_Xt[(size_t)NN * IN_DIM];     // tf32-rounded x [2048][1024]
__device__ float g_W12t[(size_t)L2DIM * IN_DIM];// tf32 (Wg1@Wl2)^T [64][1024]
__device__ float g_Yt[(size_t)L2DIM * NN];      // tf32 (dc ⊙ x@W12)^T [64][2048]
__device__ float g_Hp[NSPL][(size_t)NN * L2DIM];// A@Y split-K partials (fp32)
__device__ float g_HW[(size_t)NN * NCLS];       // dc-scaled hid@Wg2
__device__ float g_rowsum[NN];
__device__ float g_colsum[NN];

__device__ __forceinline__ float rsqrt_pos(float v) {
    return v > 0.f ? rsqrtf(v) : 0.f;
}
__device__ __forceinline__ uint32_t f2tf32(float f) {
    uint32_t u;
    asm("cvt.rna.tf32.f32 %0, %1;" : "=r"(u) : "f"(f));
    return u;
}

// ---------------- async copy / ldmatrix helpers ----------------------------
__device__ __forceinline__ void cp_async16(uint32_t smem, const void* gptr) {
    asm volatile("cp.async.cg.shared.global [%0], [%1], 16;\n" ::"r"(smem), "l"(gptr));
}
__device__ __forceinline__ void cp_commit() {
    asm volatile("cp.async.commit_group;\n");
}
template <int N>
__device__ __forceinline__ void cp_wait() {
    asm volatile("cp.async.wait_group %0;\n" ::"n"(N));
}
__device__ __forceinline__ void ldsm4(uint32_t* r, uint32_t addr) {
    asm volatile("ldmatrix.sync.aligned.m8n8.x4.shared.b16 {%0,%1,%2,%3}, [%4];"
                 : "=r"(r[0]), "=r"(r[1]), "=r"(r[2]), "=r"(r[3]) : "r"(addr));
}
__device__ __forceinline__ void mma_tf32(float* c,
                                         const uint32_t* a,
                                         uint32_t b0, uint32_t b1) {
    asm volatile(
        "mma.sync.aligned.m16n8k8.row.col.f32.tf32.tf32.f32 "
        "{%0,%1,%2,%3}, {%4,%5,%6,%7}, {%8,%9}, {%0,%1,%2,%3};"
        : "+f"(c[0]), "+f"(c[1]), "+f"(c[2]), "+f"(c[3])
        : "r"(a[0]), "r"(a[1]), "r"(a[2]), "r"(a[3]), "r"(b0), "r"(b1));
}

// ---------------- kernel 1: edge MLP (rows) + round x + W12t ---------------
// blocks 0..2047: one A-row each (R7-proven form), zero colsum[i]
// blocks 2048..2559: tf32-round x
// blocks 2560..2687: W12t[c][r] = tf32(sum_k Wg1[r][k]*Wl2[k][c]), 8 rows/blk
__global__ __launch_bounds__(256) void edge_kernel(
    const float* __restrict__ adj, const float* __restrict__ xdeg,
    const float* __restrict__ ydeg, const float* __restrict__ Wm1,
    const float* __restrict__ bm1, const float* __restrict__ Wm2,
    const float* __restrict__ bm2, const float* __restrict__ x,
    const float* __restrict__ Wg1, const float* __restrict__ Wl2) {
    int b = blockIdx.x;
    int tid = threadIdx.x;
    if (b < NN) {
        __shared__ float sW1[48], sb1[16], sdw[16], sb2[2];
        if (tid < 48) sW1[tid] = Wm1[tid];
        if (tid < 16) sb1[tid] = bm1[tid];
        if (tid < 16) sdw[tid] = Wm2[2 * tid + 1] - Wm2[2 * tid];
        if (tid < 2)  sb2[tid] = bm2[tid];
        int i = b;
        if (tid == 0) g_colsum[i] = 0.f;   // colsum_kernel runs strictly after
        __syncthreads();

        const float* arow = adj  + (size_t)i * NN;
        const float* xrow = xdeg + (size_t)i * NN;
        const float* yrow = ydeg + (size_t)i * NN;
        float* Arow = g_A + (size_t)i * NN;
        const float db = sb2[1] - sb2[0];

        float rsum = 0.f;
#pragma unroll
        for (int t = 0; t < NN / 256; t++) {
            int j = tid + t * 256;
            float a = arow[j], xd = xrow[j], yd = yrow[j];
            float dl = db;
#pragma unroll
            for (int k = 0; k < MLPW; k++) {
                float h = fmaf(a, sW1[k], fmaf(xd, sW1[16 + k], fmaf(yd, sW1[32 + k], sb1[k])));
                h = fmaxf(h, 0.f);
                dl = fmaf(h, sdw[k], dl);
            }
            float d = 0.5f * dl;
            float th;
            asm("tanh.approx.f32 %0, %1;" : "=f"(th) : "f"(d));
            float mask = fmaf(0.5f, th, 0.5f);
            float Av = a * mask + (j == i ? 1.f : 0.f);
            Av = __uint_as_float(f2tf32(Av));
            Arow[j] = Av;
            rsum += Av;
        }
        for (int off = 16; off; off >>= 1) rsum += __shfl_down_sync(0xffffffffu, rsum, off);
        __shared__ float red[8];
        if ((tid & 31) == 0) red[tid >> 5] = rsum;
        __syncthreads();
        if (tid == 0) {
            float s = 0.f;
#pragma unroll
            for (int w = 0; w < 8; w++) s += red[w];
            g_rowsum[i] = s;
        }
    } else if (b < NN + 512) {
        size_t idx4 = (size_t)(b - NN) * 1024 + tid;
        const float4* src = reinterpret_cast<const float4*>(x);
        float4* dst = reinterpret_cast<float4*>(g_Xt);
#pragma unroll
        for (int t = 0; t < 4; t++) {
            float4 v = src[idx4 + t * 256];
            uint4 u;
            u.x = f2tf32(v.x); u.y = f2tf32(v.y); u.z = f2tf32(v.z); u.w = f2tf32(v.w);
            dst[idx4 + t * 256] = *reinterpret_cast<float4*>(&u);
        }
    } else {
        // W12t: 128 blocks, each computes rows [rbase, rbase+8) of W12 for all 64 cols
        __shared__ float sW[8][256];
        int rbase = (b - NN - 512) * 8;
#pragma unroll
        for (int t = 0; t < 8; t++) {
            int idx = t * 256 + tid;
            sW[idx >> 8][idx & 255] = Wg1[(size_t)(rbase + (idx >> 8)) * HIDD + (idx & 255)];
        }
        __syncthreads();
        int c = tid & 63, rr = tid >> 6;   // rr 0..3
#pragma unroll
        for (int half = 0; half < 2; half++) {
            int rl = rr + half * 4;
            float acc = 0.f;
#pragma unroll 4
            for (int k = 0; k < HIDD; k++)
                acc = fmaf(sW[rl][k], __ldg(&Wl2[k * L2DIM + c]), acc);
            g_W12t[(size_t)c * IN_DIM + rbase + rl] = __uint_as_float(f2tf32(acc));
        }
    }
}

// ---------------- colsum: 512 CTAs, 8 rows each ----------------------------
__global__ __launch_bounds__(256) void colsum_kernel() {
    int j4 = blockIdx.x * 256 + threadIdx.x;     // 0..511 (float4 col)
    int r0 = blockIdx.y * 8;
    const float4* A4 = reinterpret_cast<const float4*>(g_A);
    float sx = 0.f, sy = 0.f, sz = 0.f, sw = 0.f;
#pragma unroll
    for (int i = 0; i < 8; i++) {
        float4 v = A4[(size_t)(r0 + i) * (NN / 4) + j4];
        sx += v.x; sy += v.y; sz += v.z; sw += v.w;
    }
    int j = j4 * 4;
    atomicAdd(&g_colsum[j + 0], sx);
    atomicAdd(&g_colsum[j + 1], sy);
    atomicAdd(&g_colsum[j + 2], sz);
    atomicAdd(&g_colsum[j + 3], sw);
}

// ---------------- tf32 tensor-core GEMM, BK=64, 2-stage, split-K CTAs -----
#define BKK 64
#define HSB 8192      // half-stage bytes per operand (64 rows * 128B)
#define OPB 16384     // per-stage per-operand bytes
#define GEMM_SMEM 65536

template <bool TRANSOUT, int NSPLIT, bool SCALE, int CSTRIDE>
__device__ __forceinline__ void gemm_body(const float* __restrict__ A,
                                          const float* __restrict__ Bt,
                                          float* __restrict__ C, int Kd,
                                          const float* __restrict__ sumvec) {
    extern __shared__ __align__(16) uint8_t smem_dyn[];
    const uint32_t sAu = (uint32_t)__cvta_generic_to_shared(smem_dyn);
    const uint32_t sBu = sAu + 2 * OPB;

    const int tid = threadIdx.x;
    const int lane = tid & 31, warp = tid >> 5;
    const int wm = warp & 1, wn = (warp >> 1) & 1, kg = warp >> 2;  // kg 0..1
    const int gid = lane >> 2, tig = lane & 3;
    const int mi = lane >> 3, lr = lane & 7;
    const int bm0 = blockIdx.y * 64, bn0 = blockIdx.x * 64;
    const int kbase = (NSPLIT > 1) ? blockIdx.z * (Kd / NSPLIT) : 0;

    const int ld_row = tid >> 2;           // 0..63
    const int qb = (tid & 3) << 1;         // 0,2,4,6
    const uint32_t off0 = ld_row * 128 + (((qb + 0) ^ (ld_row & 7)) << 4);
    const uint32_t off1 = ld_row * 128 + (((qb + 1) ^ (ld_row & 7)) << 4);
    const float* Ag = A + (size_t)(bm0 + ld_row) * Kd + kbase;
    const float* Bg = Bt + (size_t)(bn0 + ld_row) * Kd + kbase;

    const int arow = wm * 32 + ((mi & 1) << 3) + lr;
    const int brow = wn * 32 + ((mi >> 1) << 3) + lr;
    const uint32_t axr = arow & 7, bxr = brow & 7;
    const uint32_t qselA = mi >> 1, qselB = mi & 1;
    const uint32_t aOff0 = arow * 128, aOff1 = aOff0 + 16 * 128;
    const uint32_t bOff0 = brow * 128, bOff1 = bOff0 + 16 * 128;
    const uint32_t aqj[2] = {(((uint32_t)(kg * 2 + 0) * 2 + qselA) ^ axr) << 4,
                             (((uint32_t)(kg * 2 + 1) * 2 + qselA) ^ axr) << 4};
    const uint32_t bqj[2] = {(((uint32_t)(kg * 2 + 0) * 2 + qselB) ^ bxr) << 4,
                             (((uint32_t)(kg * 2 + 1) * 2 + qselB) ^ bxr) << 4};

    auto issue = [&](int kt, int s) {
#pragma unroll
        for (int h = 0; h < 2; h++) {
            const float* ag = Ag + (size_t)kt * BKK + h * 32;
            const float* bg = Bg + (size_t)kt * BKK + h * 32;
            uint32_t da = sAu + s * OPB + h * HSB;
            uint32_t db = sBu + s * OPB + h * HSB;
            cp_async16(da + off0, ag + qb * 4);
            cp_async16(da + off1, ag + qb * 4 + 4);
            cp_async16(db + off0, bg + qb * 4);
            cp_async16(db + off1, bg + qb * 4 + 4);
        }
    };

    const int niter = (Kd / NSPLIT) / BKK;
    issue(0, 0);
    cp_commit();

    float acc[2][4][4] = {};

    for (int i = 0; i < niter; i++) {
        cp_wait<0>();
        __syncthreads();
        if (i + 1 < niter) { issue(i + 1, (i + 1) & 1); cp_commit(); }
        const int s = i & 1;
#pragma unroll
        for (int h = 0; h < 2; h++) {
            const uint32_t sAs = sAu + s * OPB + h * HSB;
            const uint32_t sBs = sBu + s * OPB + h * HSB;
#pragma unroll
            for (int jj = 0; jj < 2; jj++) {
                uint32_t af0[4], af1[4], bf0[4], bf1[4];
                ldsm4(af0, sAs + aOff0 + aqj[jj]);
                ldsm4(af1, sAs + aOff1 + aqj[jj]);
                ldsm4(bf0, sBs + bOff0 + bqj[jj]);
                ldsm4(bf1, sBs + bOff1 + bqj[jj]);
                mma_tf32(acc[0][0], af0, bf0[0], bf0[1]);
                mma_tf32(acc[0][1], af0, bf0[2], bf0[3]);
                mma_tf32(acc[0][2], af0, bf1[0], bf1[1]);
                mma_tf32(acc[0][3], af0, bf1[2], bf1[3]);
                mma_tf32(acc[1][0], af1, bf0[0], bf0[1]);
                mma_tf32(acc[1][1], af1, bf0[2], bf0[3]);
                mma_tf32(acc[1][2], af1, bf1[0], bf1[1]);
                mma_tf32(acc[1][3], af1, bf1[2], bf1[3]);
            }
        }
    }

    // ---- 2-way K-split reduction through smem -----------------------------
    __syncthreads();
    float* sred = reinterpret_cast<float*>(smem_dyn);
    const int pi = wm * 2 + wn;
    if (kg == 1) {
#pragma unroll
        for (int mt = 0; mt < 2; mt++)
#pragma unroll
            for (int nt = 0; nt < 4; nt++) {
                int r = mt * 16 + gid, c = nt * 8 + 2 * tig;
                float* base = sred + pi * 1056;
                base[r * 33 + c] = acc[mt][nt][0];
                base[r * 33 + c + 1] = acc[mt][nt][1];
                base[(r + 8) * 33 + c] = acc[mt][nt][2];
                base[(r + 8) * 33 + c + 1] = acc[mt][nt][3];
            }
    }
    __syncthreads();
    if (kg == 0) {
#pragma unroll
        for (int mt = 0; mt < 2; mt++) {
            int r = mt * 16 + gid;
            const float* base = sred + pi * 1056;
            int gr0 = bm0 + wm * 32 + r;
            int gr1 = gr0 + 8;
            float s0 = SCALE ? rsqrt_pos(sumvec[gr0]) : 1.f;
            float s1 = SCALE ? rsqrt_pos(sumvec[gr1]) : 1.f;
#pragma unroll
            for (int nt = 0; nt < 4; nt++) {
                int c = nt * 8 + 2 * tig;
                float v00 = (acc[mt][nt][0] + base[r * 33 + c]) * s0;
                float v01 = (acc[mt][nt][1] + base[r * 33 + c + 1]) * s0;
                float v10 = (acc[mt][nt][2] + base[(r + 8) * 33 + c]) * s1;
                float v11 = (acc[mt][nt][3] + base[(r + 8) * 33 + c + 1]) * s1;
                if (TRANSOUT) {
                    int n0 = bn0 + wn * 32 + c;
                    C[(size_t)n0 * NN + gr0] = __uint_as_float(f2tf32(v00));
                    C[(size_t)(n0 + 1) * NN + gr0] = __uint_as_float(f2tf32(v01));
                    C[(size_t)n0 * NN + gr1] = __uint_as_float(f2tf32(v10));
                    C[(size_t)(n0 + 1) * NN + gr1] = __uint_as_float(f2tf32(v11));
                } else {
                    int col = bn0 + wn * 32 + c;
                    *reinterpret_cast<float2*>(&C[(size_t)gr0 * CSTRIDE + col]) =
                        make_float2(v00, v01);
                    *reinterpret_cast<float2*>(&C[(size_t)gr1 * CSTRIDE + col]) =
                        make_float2(v10, v11);
                }
            }
        }
    }
}

// Y: g_Yt = (dc ⊙ (x @ W12))^T [64][2048], tf32; M=2048 N=64 K=1024
__global__ __launch_bounds__(256) void y_kernel() {
    gemm_body<true, 1, true, 0>(g_Xt, g_W12t, g_Yt, IN_DIM, g_colsum);
}
// HID-GEMM: g_Hp[z] = (g_A @ Y) partial over K-eighth z; M=2048 N=64 K=2048
__global__ __launch_bounds__(256) void hidg_kernel() {
    gemm_body<false, NSPL, false, L2DIM>(g_A, g_Yt, g_Hp[blockIdx.z], NN, nullptr);
}

// ---------------- finish: hid = dr*sum_z Hp + bl2;  HW = dc*(hid@Wg2) ------
__global__ __launch_bounds__(256) void hid_finish_kernel(const float* __restrict__ bl2,
                                                         const float* __restrict__ Wg2,
                                                         float* __restrict__ hid_out) {
    __shared__ float sHid[16][L2DIM + 1];
    int tid = threadIdx.x;
    int rowbase = blockIdx.x * 16;

    int c = tid & 63;
    int rq = tid >> 6;   // 0..3
    float b = bl2[c];
#pragma unroll
    for (int it = 0; it < 4; it++) {
        int row = it * 4 + rq;
        size_t idx = (size_t)(rowbase + row) * L2DIM + c;
        float v = 0.f;
#pragma unroll
        for (int z = 0; z < NSPL; z++) v += g_Hp[z][idx];
        v = v * rsqrt_pos(g_rowsum[rowbase + row]) + b;
        hid_out[idx] = v;
        sHid[row][c] = v;
    }
    __syncthreads();
    if (tid < 64) {
        int r = tid >> 2, cls = tid & 3;
        float s = 0.f;
#pragma unroll
        for (int k = 0; k < L2DIM; k++) s = fmaf(sHid[r][k], Wg2[k * NCLS + cls], s);
        g_HW[(size_t)(rowbase + r) * NCLS + cls] = s * rsqrt_pos(g_colsum[rowbase + r]);
    }
}

// ---------------- out[i] = dr[i] * sum_j A[i,j] * HW[j] --------------------
__global__ __launch_bounds__(256) void out_kernel(float* __restrict__ out) {
    int tid = threadIdx.x;
    __shared__ float sHWt[NCLS][NN];
    const float4* hw4 = reinterpret_cast<const float4*>(g_HW);
#pragma unroll
    for (int t = 0; t < NN / 256; t++) {
        int j = tid + t * 256;
        float4 h = hw4[j];            // HW row j: 4 classes
        sHWt[0][j] = h.x; sHWt[1][j] = h.y; sHWt[2][j] = h.z; sHWt[3][j] = h.w;
    }
    __syncthreads();

    const float4* A4 = reinterpret_cast<const float4*>(g_A);
    __shared__ float red[8][4];
    for (int r = 0; r < 8; r++) {
        int i = blockIdx.x * 8 + r;
        float ax = 0.f, ay = 0.f, az = 0.f, aw = 0.f;
#pragma unroll
        for (int t = 0; t < NN / 1024; t++) {
            int j4 = tid + t * 256;
            float4 a = A4[(size_t)i * (NN / 4) + j4];
            const float4 h0 = *reinterpret_cast<const float4*>(&sHWt[0][j4 * 4]);
            const float4 h1 = *reinterpret_cast<const float4*>(&sHWt[1][j4 * 4]);
            const float4 h2 = *reinterpret_cast<const float4*>(&sHWt[2][j4 * 4]);
            const float4 h3 = *reinterpret_cast<const float4*>(&sHWt[3][j4 * 4]);
            ax += a.x * h0.x + a.y * h0.y + a.z * h0.z + a.w * h0.w;
            ay += a.x * h1.x + a.y * h1.y + a.z * h1.z + a.w * h1.w;
            az += a.x * h2.x + a.y * h2.y + a.z * h2.z + a.w * h2.w;
            aw += a.x * h3.x + a.y * h3.y + a.z * h3.z + a.w * h3.w;
        }
        for (int off = 16; off; off >>= 1) {
            ax += __shfl_down_sync(0xffffffffu, ax, off);
            ay += __shfl_down_sync(0xffffffffu, ay, off);
            az += __shfl_down_sync(0xffffffffu, az, off);
            aw += __shfl_down_sync(0xffffffffu, aw, off);
        }
        if ((tid & 31) == 0) {
            int w = tid >> 5;
            red[w][0] = ax; red[w][1] = ay; red[w][2] = az; red[w][3] = aw;
        }
        __syncthreads();
        if (tid < 4) {
            float s = 0.f;
#pragma unroll
            for (int w = 0; w < 8; w++) s += red[w][tid];
            out[i * NCLS + tid] = rsqrt_pos(g_rowsum[i]) * s;
        }
        __syncthreads();
    }
}

// ---------------- launch (single stream, 6 kernels) ------------------------
extern "C" void kernel_launch(void* const* d_in, const int* in_sizes, int n_in,
                              void* d_out, int out_size) {
    const float* x    = (const float*)d_in[0];
    const float* adj  = (const float*)d_in[1];
    const float* xdeg = (const float*)d_in[2];
    const float* ydeg = (const float*)d_in[3];
    const float* Wm1  = (const float*)d_in[4];
    const float* bm1  = (const float*)d_in[5];
    const float* Wm2  = (const float*)d_in[6];
    const float* bm2  = (const float*)d_in[7];
    const float* Wg1  = (const float*)d_in[8];
    const float* Wl2  = (const float*)d_in[9];
    const float* bl2  = (const float*)d_in[10];
    const float* Wg2  = (const float*)d_in[11];

    float* out = (float*)d_out;               // [2048, 4]
    float* hid = out + (size_t)NN * NCLS;     // [2048, 64]

    static bool attr_done = false;
    if (!attr_done) {   // first call is the (uncaptured) correctness run
        cudaFuncSetAttribute(y_kernel,
                             cudaFuncAttributeMaxDynamicSharedMemorySize, GEMM_SMEM);
        cudaFuncSetAttribute(hidg_kernel,
                             cudaFuncAttributeMaxDynamicSharedMemorySize, GEMM_SMEM);
        attr_done = true;
    }

    edge_kernel<<<NN + 512 + 128, 256>>>(adj, xdeg, ydeg, Wm1, bm1, Wm2, bm2,
                                         x, Wg1, Wl2);
    colsum_kernel<<<dim3(2, 256), 256>>>();
    y_kernel<<<dim3(1, NN / 64, 1), 256, GEMM_SMEM>>>();
    hidg_kernel<<<dim3(1, NN / 64, NSPL), 256, GEMM_SMEM>>>();
    hid_finish_kernel<<<NN / 16, 256>>>(bl2, Wg2, hid);
    out_kernel<<<NN / 8, 256>>>(out);
}